// round 3
// baseline (speedup 1.0000x reference)
#include <cuda_runtime.h>
#include <cstdint>

#define B_   256
#define T_   2048
#define IN_  128
#define H_   64
#define G_   256   // 4*H

// Scratch (allocation-free rule: static __device__ arrays)
__device__ float g_xp[(size_t)B_ * T_ * G_];   // precomputed x@W_ih1^T + b_ih1 + b_hh1
__device__ float g_Wt[IN_ * G_];               // W_ih1 transposed: [k][g]

typedef unsigned long long u64;

// ---------------- helpers ----------------
__device__ __forceinline__ void ffma2(u64& d, u64 a, u64 b) {
    asm("fma.rn.f32x2 %0, %1, %2, %0;" : "+l"(d) : "l"(a), "l"(b));
}
__device__ __forceinline__ float2 unpk(u64 p) {
    float2 r;
    asm("mov.b64 {%0, %1}, %2;" : "=f"(r.x), "=f"(r.y) : "l"(p));
    return r;
}
__device__ __forceinline__ u64 dup2(float a) {
    u64 r;
    asm("mov.b64 %0, {%1, %1};" : "=l"(r) : "f"(a));
    return r;
}
__device__ __forceinline__ float sigf(float x) {
    return __fdividef(1.0f, 1.0f + __expf(-x));
}
__device__ __forceinline__ float tanhf_(float x) {
    float a = fabsf(x);
    float e = __expf(2.0f * a);                 // inf-safe
    float r = 1.0f - __fdividef(2.0f, e + 1.0f);
    return copysignf(r, x);
}

// ---------------- kernel 1: transpose W_ih1 into k-major ----------------
__global__ void wt_kernel(const float* __restrict__ W) {
    int i = blockIdx.x * 256 + threadIdx.x;    // 32768 elems
    int n = i >> 7;
    int k = i & 127;
    g_Wt[k * G_ + n] = W[n * IN_ + k];
}

// ---------------- kernel 2: xp = x @ W_ih1^T + b_ih1 + b_hh1 ----------------
__global__ __launch_bounds__(256) void xp_gemm(const float* __restrict__ x,
                                               const float* __restrict__ bih,
                                               const float* __restrict__ bhh) {
    __shared__ float Xs[64][128];              // 32 KB
    int tid = threadIdx.x;
    size_t mbase = (size_t)blockIdx.x * 64;
    int nbase = blockIdx.y * 64;

    const float* xg = x + mbase * IN_;
#pragma unroll
    for (int i = 0; i < 8; i++) {
        int idx = tid + i * 256;
        int m = idx >> 5, k4 = (idx & 31) << 2;
        *(float4*)&Xs[m][k4] = *(const float4*)(xg + m * IN_ + k4);
    }
    __syncthreads();

    int tx = tid & 15, ty = tid >> 4;
    int n0 = nbase + tx * 4;
    int m0 = ty * 4;

    u64 acc[4][2];
#pragma unroll
    for (int i = 0; i < 4; i++) { acc[i][0] = 0ull; acc[i][1] = 0ull; }

    const float* wt = g_Wt + n0;
#pragma unroll 8
    for (int k = 0; k < IN_; k++) {
        ulonglong2 bb = *(const ulonglong2*)(wt + k * G_);
#pragma unroll
        for (int i = 0; i < 4; i++) {
            u64 ap = dup2(Xs[m0 + i][k]);
            ffma2(acc[i][0], ap, bb.x);
            ffma2(acc[i][1], ap, bb.y);
        }
    }

    float4 bs;
    bs.x = bih[n0 + 0] + bhh[n0 + 0];
    bs.y = bih[n0 + 1] + bhh[n0 + 1];
    bs.z = bih[n0 + 2] + bhh[n0 + 2];
    bs.w = bih[n0 + 3] + bhh[n0 + 3];
#pragma unroll
    for (int i = 0; i < 4; i++) {
        float2 p0 = unpk(acc[i][0]);
        float2 p1 = unpk(acc[i][1]);
        float4 o = make_float4(p0.x + bs.x, p0.y + bs.y, p1.x + bs.z, p1.y + bs.w);
        *(float4*)(g_xp + (mbase + m0 + i) * G_ + n0) = o;
    }
}

// ---------------- kernel 3: fused 2-layer LSTM recurrence + output head ----------------
// 128 CTAs x 512 threads, 2 batch rows per CTA (both rows per thread).
// Thread tid: q = tid>>3 (gate quad, gates 4q..4q+3), s = tid&7 (K split).
//   Layer-1 dot: k in [8s, 8s+8)  over h1 (64).
//   Layer-2 dot: kcat in [16s, 16s+16) over concat [h1new(64); h2prev(64)].
// Per-thread register weights: 4*8 + 4*16 = 96 floats = 48 u64 regs (no spills).
// Gate partials combined with 3-level shfl_xor butterfly (s is lane bits [0,3)).
// Dedicated 128 threads do activations; they also prefetch xp from gmem.
__global__ __launch_bounds__(512, 1) void lstm_rec(
    const float* __restrict__ Whh1, const float* __restrict__ Wih2,
    const float* __restrict__ Whh2, const float* __restrict__ bih2,
    const float* __restrict__ bhh2, const float* __restrict__ Wout,
    const float* __restrict__ bout, float* __restrict__ out) {
    __shared__ float h1s[2][64];      // [row][unit]  (single buffer; barrier-ordered)
    __shared__ float h2s[2][64];
    __shared__ float ga[2][256];      // [row][gate]
    __shared__ float gb[2][256];
    __shared__ float b2s[256];        // bias2 sums
    __shared__ float red[4];

    int tid = threadIdx.x;
    int q = tid >> 3, s = tid & 7;
    int g0 = q * 4;

    // ---- weights into registers ----
    u64 w1[4][4];    // [gate][k-pair], k in [8s, 8s+8)
    u64 w2[4][8];    // [gate][kc-pair], kcat in [16s, 16s+16)
#pragma unroll
    for (int g = 0; g < 4; g++) {
        const u64* p1 = (const u64*)(Whh1 + (g0 + g) * 64 + s * 8);
#pragma unroll
        for (int j = 0; j < 4; j++) w1[g][j] = p1[j];
        const float* b2 = (s < 4) ? (Wih2 + (g0 + g) * 64 + s * 16)
                                  : (Whh2 + (g0 + g) * 64 + (s - 4) * 16);
        const u64* p2 = (const u64*)b2;
#pragma unroll
        for (int j = 0; j < 8; j++) w2[g][j] = p2[j];
    }
    if (tid < 256) b2s[tid] = bih2[tid] + bhh2[tid];

    // activation-thread state (tid < 128): row ur, unit uu
    int ur = tid >> 6, uu = tid & 63;
    float wo = (tid < 128) ? Wout[uu] : 0.0f;
    float bo = bout[0];
    float c1v = 0.0f, c2v = 0.0f;

    int b0 = blockIdx.x * 2;
    // xp prefetch handled by activation threads: 4 gate values for (ur,uu)
    const float* xpu = g_xp + ((size_t)(b0 + ur) * T_) * G_ + uu;
    float xq0 = 0.f, xq1 = 0.f, xq2 = 0.f, xq3 = 0.f;
    if (tid < 128) {
        xq0 = xpu[0]; xq1 = xpu[64]; xq2 = xpu[128]; xq3 = xpu[192];
        h1s[ur][uu] = 0.0f;
        h2s[ur][uu] = 0.0f;
    }
    __syncthreads();

    for (int t = 0; t < T_; t++) {
        // ---- P1: layer-1 recurrent gate partial dots ----
        u64 a[8];   // [2*g + row]
#pragma unroll
        for (int i = 0; i < 8; i++) a[i] = 0ull;
        {
            const ulonglong2* hA = (const ulonglong2*)&h1s[0][s * 8];
            const ulonglong2* hB = (const ulonglong2*)&h1s[1][s * 8];
#pragma unroll
            for (int j = 0; j < 2; j++) {
                ulonglong2 u0 = hA[j];
                ulonglong2 u1 = hB[j];
#pragma unroll
                for (int g = 0; g < 4; g++) {
                    ffma2(a[2 * g + 0], w1[g][2 * j], u0.x);
                    ffma2(a[2 * g + 0], w1[g][2 * j + 1], u0.y);
                    ffma2(a[2 * g + 1], w1[g][2 * j], u1.x);
                    ffma2(a[2 * g + 1], w1[g][2 * j + 1], u1.y);
                }
            }
        }
        float v[8];
#pragma unroll
        for (int i = 0; i < 8; i++) {
            float2 f = unpk(a[i]);
            v[i] = f.x + f.y;
            v[i] += __shfl_xor_sync(0xffffffffu, v[i], 1);
            v[i] += __shfl_xor_sync(0xffffffffu, v[i], 2);
            v[i] += __shfl_xor_sync(0xffffffffu, v[i], 4);
        }
        if (s == 0) {
            *(float4*)&ga[0][g0] = make_float4(v[0], v[2], v[4], v[6]);
            *(float4*)&ga[1][g0] = make_float4(v[1], v[3], v[5], v[7]);
        }
        __syncthreads();

        // ---- U1: layer-1 activations (+ xp add) ----
        if (tid < 128) {
            float iv = sigf(ga[ur][uu] + xq0);
            float fv = sigf(ga[ur][64 + uu] + xq1);
            float gv = tanhf_(ga[ur][128 + uu] + xq2);
            float ov = sigf(ga[ur][192 + uu] + xq3);
            c1v = fv * c1v + iv * gv;
            h1s[ur][uu] = ov * tanhf_(c1v);
            if (t + 1 < T_) {                  // prefetch next step's xp
                const float* xn = xpu + (size_t)(t + 1) * G_;
                xq0 = xn[0]; xq1 = xn[64]; xq2 = xn[128]; xq3 = xn[192];
            }
        }
        __syncthreads();

        // ---- P2: layer-2 gate partial dots over concat [h1new; h2prev] ----
#pragma unroll
        for (int i = 0; i < 8; i++) a[i] = 0ull;
        {
            const ulonglong2* pA;
            const ulonglong2* pB;
            if (s < 4) {
                pA = (const ulonglong2*)&h1s[0][s * 16];
                pB = (const ulonglong2*)&h1s[1][s * 16];
            } else {
                pA = (const ulonglong2*)&h2s[0][(s - 4) * 16];
                pB = (const ulonglong2*)&h2s[1][(s - 4) * 16];
            }
#pragma unroll
            for (int j = 0; j < 4; j++) {
                ulonglong2 u0 = pA[j];
                ulonglong2 u1 = pB[j];
#pragma unroll
                for (int g = 0; g < 4; g++) {
                    ffma2(a[2 * g + 0], w2[g][2 * j], u0.x);
                    ffma2(a[2 * g + 0], w2[g][2 * j + 1], u0.y);
                    ffma2(a[2 * g + 1], w2[g][2 * j], u1.x);
                    ffma2(a[2 * g + 1], w2[g][2 * j + 1], u1.y);
                }
            }
        }
#pragma unroll
        for (int i = 0; i < 8; i++) {
            float2 f = unpk(a[i]);
            v[i] = f.x + f.y;
            v[i] += __shfl_xor_sync(0xffffffffu, v[i], 1);
            v[i] += __shfl_xor_sync(0xffffffffu, v[i], 2);
            v[i] += __shfl_xor_sync(0xffffffffu, v[i], 4);
        }
        if (s == 0) {
            *(float4*)&gb[0][g0] = make_float4(v[0], v[2], v[4], v[6]);
            *(float4*)&gb[1][g0] = make_float4(v[1], v[3], v[5], v[7]);
        }
        __syncthreads();

        // ---- U2: layer-2 activations + output-head partials ----
        if (tid < 128) {
            float iv = sigf(gb[ur][uu] + b2s[uu]);
            float fv = sigf(gb[ur][64 + uu] + b2s[64 + uu]);
            float gv = tanhf_(gb[ur][128 + uu] + b2s[128 + uu]);
            float ov = sigf(gb[ur][192 + uu] + b2s[192 + uu]);
            c2v = fv * c2v + iv * gv;
            float h2v = ov * tanhf_(c2v);
            h2s[ur][uu] = h2v;
            float p = wo * h2v;
#pragma unroll
            for (int off = 16; off > 0; off >>= 1)
                p += __shfl_xor_sync(0xffffffffu, p, off);
            if ((tid & 31) == 0) red[tid >> 5] = p;
        }
        __syncthreads();

        if (tid < 2) {
            float r = red[2 * tid] + red[2 * tid + 1] + bo;
            r = fminf(fmaxf(r, 0.0f), 1.0f);
            out[(size_t)(b0 + tid) * T_ + t] = r;
        }
    }
}

// ---------------- launch ----------------
extern "C" void kernel_launch(void* const* d_in, const int* in_sizes, int n_in,
                              void* d_out, int out_size) {
    const float* x    = (const float*)d_in[0];
    const float* Wih1 = (const float*)d_in[1];
    const float* Whh1 = (const float*)d_in[2];
    const float* bih1 = (const float*)d_in[3];
    const float* bhh1 = (const float*)d_in[4];
    const float* Wih2 = (const float*)d_in[5];
    const float* Whh2 = (const float*)d_in[6];
    const float* bih2 = (const float*)d_in[7];
    const float* bhh2 = (const float*)d_in[8];
    const float* Wout = (const float*)d_in[9];
    const float* bout = (const float*)d_in[10];
    float* out = (float*)d_out;

    wt_kernel<<<128, 256>>>(Wih1);
    xp_gemm<<<dim3((B_ * T_) / 64, G_ / 64), 256>>>(x, bih1, bhh1);
    lstm_rec<<<128, 512>>>(Whh1, Wih2, Whh2, bih2, bhh2, Wout, bout, out);
    (void)in_sizes; (void)n_in; (void)out_size;
}